// round 4
// baseline (speedup 1.0000x reference)
#include <cuda_runtime.h>
#include <math.h>

#define NL   1200
#define NS   5
#define NPTS (NL*NS)     // 6000
#define DD   128
#define HH   128
#define WW   128
#define TK   10
#define GAPF 0.1f

// ---------------- scratch (static __device__, no allocations) ----------------
static __device__ float g_d1[NPTS*DD];     // normalized descriptors set1 [point][dim]
static __device__ float g_d2[NPTS*DD];     // set2
static __device__ float g_ns[2][NL];       // nsamp per line (float, integer-valued 2..5)
static __device__ float g_ls [NL*NL];      // line_scores[i][j]
static __device__ float g_lsT[NL*NL];      // transpose, for direction-2 topk
static __device__ int   g_topk[2][NL*TK];  // top-10 indices, pos 9 = largest (argsort order)
static __device__ float g_nw [2][NL*2*TK]; // NW scores, [line][t] t in 0..19 (10..19 = flipped)
static __device__ int   g_match[2][NL];

// Unfused helpers (match XLA's per-op rounding; no FMA contraction)
__device__ __forceinline__ float fm(float a, float b) { return __fmul_rn(a, b); }
__device__ __forceinline__ float fa(float a, float b) { return __fadd_rn(a, b); }
__device__ __forceinline__ float fs(float a, float b) { return __fsub_rn(a, b); }

// ---------------- kernel 1: sample points + bilinear descriptors -------------
__device__ __forceinline__ float gat(const float* img, int x, int y) {
    if (x < 0 || x >= WW || y < 0 || y >= HH) return 0.0f;
    return img[y*WW + x];
}

__global__ void sample_kernel(const float* __restrict__ seg1,
                              const float* __restrict__ seg2,
                              const float* __restrict__ desc1,
                              const float* __restrict__ desc2) {
    int warp = (blockIdx.x * blockDim.x + threadIdx.x) >> 5;
    int lane = threadIdx.x & 31;
    if (warp >= 2*NPTS) return;
    int set  = warp / NPTS;
    int p    = warp - set*NPTS;
    int line = p / NS;
    int k    = p - line*NS;

    const float* seg  = set ? seg2  : seg1;
    const float* desc = set ? desc2 : desc1;
    float*       dout = set ? g_d2  : g_d1;

    float sy = seg[line*4+0], sx = seg[line*4+1];
    float ey = seg[line*4+2], ex = seg[line*4+3];
    float dy = fs(ey, sy), dx = fs(ex, sx);
    float len = sqrtf(fa(fm(dy, dy), fm(dx, dx)));
    float ns  = fminf(fmaxf(floorf(__fdiv_rn(len, 8.0f)), 2.0f), 5.0f);
    if (k == 0 && lane == 0) g_ns[set][line] = ns;

    float nm1 = fs(ns, 1.0f);
    float ivy = __fdiv_rn(dy, nm1);
    float ivx = __fdiv_rn(dx, nm1);
    float kf  = (float)k;
    float py  = fa(sy, fm(kf, ivy));
    float px  = fa(sx, fm(kf, ivx));
    if (!(kf < ns)) { py = 0.0f; px = 0.0f; }   // reference zeroes invalid pts

    // bilinear coords (img_h = img_w = 512); mirror reference op-for-op
    float xn  = fs(__fdiv_rn(fm(2.0f, px), (float)(WW*4 - 1)), 1.0f);
    float yn  = fs(__fdiv_rn(fm(2.0f, py), (float)(HH*4 - 1)), 1.0f);
    float ixf = __fdiv_rn(fs(fm(fa(xn, 1.0f), (float)WW), 1.0f), 2.0f);
    float iyf = __fdiv_rn(fs(fm(fa(yn, 1.0f), (float)HH), 1.0f), 2.0f);
    float x0f = floorf(ixf), y0f = floorf(iyf);
    float wx = fs(ixf, x0f), wy = fs(iyf, y0f);
    int   x0 = (int)x0f,  y0 = (int)y0f;
    float w00 = fm(fs(1.0f, wx), fs(1.0f, wy));
    float w10 = fm(wx, fs(1.0f, wy));
    float w01 = fm(fs(1.0f, wx), wy);
    float w11 = fm(wx, wy);

    // Each lane holds dims {lane, lane+32, lane+64, lane+96}; partial sum of
    // squares strided-ascending with separate mul/add, then 32-lane tree.
    float v[4];
    float ss = 0.0f;
    #pragma unroll
    for (int q = 0; q < 4; q++) {
        int d = lane + q*32;
        const float* img = desc + d*HH*WW;
        float a = fm(gat(img, x0,   y0  ), w00);
        a = fa(a, fm(gat(img, x0+1, y0  ), w10));
        a = fa(a, fm(gat(img, x0,   y0+1), w01));
        a = fa(a, fm(gat(img, x0+1, y0+1), w11));
        v[q] = a;
        ss = fa(ss, fm(a, a));
    }
    #pragma unroll
    for (int off = 16; off; off >>= 1)
        ss = fa(ss, __shfl_xor_sync(0xffffffffu, ss, off));
    float nrm = sqrtf(ss);
    #pragma unroll
    for (int q = 0; q < 4; q++)
        dout[p*DD + lane + q*32] = __fdiv_rn(v[q], nrm);   // IEEE division like XLA
}

// ------------- kernel 2: fused GEMM + 5x5-block line-score reduction ---------
// 16x16 line-pairs per block (80x80 samples), K chunks of 32; accumulation is
// sequential k=0..127 single-accumulator FFMA == cuBLAS sgemm rounding.
__global__ void ls_kernel() {
    __shared__ float s1[80][33];
    __shared__ float s2[80][33];
    const int i0 = blockIdx.y * 16;
    const int j0 = blockIdx.x * 16;
    const int t  = threadIdx.x;           // 256 threads
    const int li = t >> 4;
    const int lj = t & 15;

    float acc[5][5];
    #pragma unroll
    for (int n = 0; n < 5; n++)
        #pragma unroll
        for (int m = 0; m < 5; m++) acc[n][m] = 0.0f;

    for (int k0 = 0; k0 < DD; k0 += 32) {
        #pragma unroll
        for (int it = 0; it < 10; it++) {          // 2560 elems / 256 threads
            int idx = t + it*256;
            int r   = idx >> 5;
            int kk  = idx & 31;
            s1[r][kk] = g_d1[(i0*NS + r)*DD + k0 + kk];
            s2[r][kk] = g_d2[(j0*NS + r)*DD + k0 + kk];
        }
        __syncthreads();
        #pragma unroll
        for (int kk = 0; kk < 32; kk++) {
            float a[5], b[5];
            #pragma unroll
            for (int n = 0; n < 5; n++) a[n] = s1[li*5 + n][kk];
            #pragma unroll
            for (int m = 0; m < 5; m++) b[m] = s2[lj*5 + m][kk];
            #pragma unroll
            for (int n = 0; n < 5; n++)
                #pragma unroll
                for (int m = 0; m < 5; m++)
                    acc[n][m] = __fmaf_rn(a[n], b[m], acc[n][m]);
        }
        __syncthreads();
    }

    int nsa = (int)g_ns[0][i0 + li];
    int nsb = (int)g_ns[1][j0 + lj];

    // masked block: s[n][m] = (n<nsa && m<nsb) ? dot : -1
    float ls1s = 0.0f, c1 = 0.0f;
    #pragma unroll
    for (int n = 0; n < 5; n++) {
        float mx = -3.0e38f;
        #pragma unroll
        for (int m = 0; m < 5; m++) {
            float sv = (n < nsa && m < nsb) ? acc[n][m] : -1.0f;
            mx = fmaxf(mx, sv);
        }
        float v1 = (mx != -1.0f) ? 1.0f : 0.0f;
        ls1s = fa(ls1s, fm(mx, v1)); c1 = fa(c1, v1);
    }
    float ls2s = 0.0f, c2 = 0.0f;
    #pragma unroll
    for (int m = 0; m < 5; m++) {
        float mx = -3.0e38f;
        #pragma unroll
        for (int n = 0; n < 5; n++) {
            float sv = (n < nsa && m < nsb) ? acc[n][m] : -1.0f;
            mx = fmaxf(mx, sv);
        }
        float v2 = (mx != -1.0f) ? 1.0f : 0.0f;
        ls2s = fa(ls2s, fm(mx, v2)); c2 = fa(c2, v2);
    }
    float lsc = __fdiv_rn(fa(__fdiv_rn(ls1s, c1), __fdiv_rn(ls2s, c2)), 2.0f);
    g_ls [(i0+li)*NL + (j0+lj)] = lsc;
    g_lsT[(j0+lj)*NL + (i0+li)] = lsc;
}

// ---------------- kernel 3: top-10 selection (argsort-compatible) ------------
// Key = (monotonic float bits, index): descending selection breaks value ties
// toward larger index == last-10 of a stable ascending argsort.
__global__ void topk_kernel() {
    int row = blockIdx.x;
    int dir = blockIdx.y;
    int t   = threadIdx.x;                 // 128 threads
    const float* ls = dir ? g_lsT : g_ls;
    __shared__ unsigned long long sb[128];

    unsigned long long prev = 0xFFFFFFFFFFFFFFFFull;
    for (int s = 0; s < TK; s++) {
        unsigned long long best = 0ull;
        for (int j = t; j < NL; j += 128) {
            float v = ls[row*NL + j];
            unsigned u = __float_as_uint(v);
            u = (u & 0x80000000u) ? ~u : (u | 0x80000000u);
            unsigned long long key = ((unsigned long long)u << 32) | (unsigned)j;
            if (key < prev && key > best) best = key;
        }
        sb[t] = best;
        __syncthreads();
        #pragma unroll
        for (int off = 64; off; off >>= 1) {
            if (t < off) { if (sb[t+off] > sb[t]) sb[t] = sb[t+off]; }
            __syncthreads();
        }
        prev = sb[0];
        if (t == 0) g_topk[dir][row*TK + (TK-1-s)] = (int)(prev & 0xFFFFFFFFull);
        __syncthreads();
    }
}

// ---------------- kernel 4: recompute 5x5 blocks + Needleman-Wunsch ----------
// One warp per (dir,line,candidate). Lane l<25 computes dot (n=l/5, m=l%5)
// sequentially over k=0..127 with single-accumulator FFMA == cuBLAS rounding.
__global__ void nw_kernel() {
    int gw   = (blockIdx.x * blockDim.x + threadIdx.x) >> 5;
    int lane = threadIdx.x & 31;
    if (gw >= 2*NL*2*TK) return;
    int dir  = gw / (NL*2*TK);
    int rem  = gw - dir*(NL*2*TK);
    int line = rem / (2*TK);
    int t    = rem - line*(2*TK);
    int j    = g_topk[dir][line*TK + (t % TK)];
    int flip = (t >= TK);

    const float* dA = dir ? g_d2 : g_d1;   // row samples
    const float* dB = dir ? g_d1 : g_d2;   // col samples
    int na = (int)g_ns[dir ? 1 : 0][line];
    int nb = (int)g_ns[dir ? 0 : 1][j];

    const float* pa = dA + (line*NS)*DD;
    const float* pb = dB + (j*NS)*DD;

    int n = lane / 5, m = lane - n*5;
    float acc = 0.0f;
    if (lane < 25) {
        const float* ra = pa + n*DD;
        const float* rb = pb + m*DD;
        #pragma unroll 16
        for (int k = 0; k < DD; k++)
            acc = __fmaf_rn(ra[k], rb[k], acc);
    }

    // Broadcast the 25 dots to ALL lanes (every lane must execute each shfl).
    float blk[25];
    #pragma unroll
    for (int i = 0; i < 25; i++)
        blk[i] = __shfl_sync(0xffffffffu, acc, i);

    if (lane == 0) {
        float prev[6] = {0,0,0,0,0,0};
        #pragma unroll
        for (int r = 0; r < 5; r++) {
            float cur[6]; cur[0] = 0.0f;
            #pragma unroll
            for (int c = 0; c < 5; c++) {
                int sm = flip ? (4 - c) : c;
                float sv = (r < na && sm < nb) ? blk[r*5 + sm] : -1.0f;
                sv = fs(sv, GAPF);
                cur[c+1] = fmaxf(fmaxf(cur[c], prev[c+1]), fa(prev[c], sv));
            }
            #pragma unroll
            for (int c = 0; c < 6; c++) prev[c] = cur[c];
        }
        g_nw[dir][line*2*TK + t] = prev[5];
    }
}

// ---------------- kernel 5: argmax over 20 candidates ------------------------
__global__ void argmax_kernel() {
    int idx = blockIdx.x * blockDim.x + threadIdx.x;
    if (idx >= 2*NL) return;
    int dir = idx / NL, line = idx - dir*NL;
    const float* nw = &g_nw[dir][line*2*TK];
    float best = nw[0]; int bi = 0;
    for (int t = 1; t < 2*TK; t++)
        if (nw[t] > best) { best = nw[t]; bi = t; }   // first-occurrence argmax
    g_match[dir][line] = g_topk[dir][line*TK + (bi % TK)];
}

// ---------------- kernel 6: mutual check + write output ----------------------
// out layout (float32): [0,1200) matches, [1200, 25200) nw (dir-1), row-major.
__global__ void final_kernel(float* __restrict__ out, int out_size) {
    int idx = blockIdx.x * blockDim.x + threadIdx.x;
    if (idx >= NL + NL*2*TK || idx >= out_size) return;
    if (idx < NL) {
        int m  = g_match[0][idx];
        int ok = (g_match[1][m] == idx);
        out[idx] = ok ? (float)m : -1.0f;
    } else {
        out[idx] = g_nw[0][idx - NL];
    }
}

// ---------------- launcher ---------------------------------------------------
extern "C" void kernel_launch(void* const* d_in, const int* in_sizes, int n_in,
                              void* d_out, int out_size) {
    const float* seg1  = (const float*)d_in[0];
    const float* seg2  = (const float*)d_in[1];
    const float* desc1 = (const float*)d_in[2];
    const float* desc2 = (const float*)d_in[3];

    {   // 2*6000 points, one warp each
        int warps = 2*NPTS;
        int threads = warps*32;
        sample_kernel<<<(threads + 255)/256, 256>>>(seg1, seg2, desc1, desc2);
    }
    {
        dim3 g(NL/16, NL/16);
        ls_kernel<<<g, 256>>>();
    }
    topk_kernel<<<dim3(NL, 2), 128>>>();
    {
        int warps = 2*NL*2*TK;
        nw_kernel<<<(warps*32 + 255)/256, 256>>>();
    }
    argmax_kernel<<<(2*NL + 255)/256, 256>>>();
    final_kernel<<<(NL + NL*2*TK + 255)/256, 256>>>((float*)d_out, out_size);
}

// round 5
// speedup vs baseline: 1.1804x; 1.1804x over previous
#include <cuda_runtime.h>
#include <math.h>

#define NL   1200
#define NS   5
#define NPTS (NL*NS)     // 6000
#define DD   128
#define HH   128
#define WW   128
#define TK   10
#define GAPF 0.1f

// ---------------- scratch (static __device__, no allocations) ----------------
static __device__ float g_d1[NPTS*DD];     // normalized descriptors set1 [point][dim]
static __device__ float g_d2[NPTS*DD];     // set2
static __device__ float g_ns[2][NL];       // nsamp per line (float, integer-valued 2..5)
static __device__ float g_ls [NL*NL];      // line_scores[i][j]
static __device__ float g_lsT[NL*NL];      // transpose, for direction-2 topk
static __device__ int   g_topk[2][NL*TK];  // top-10 indices, pos 9 = largest (argsort order)
static __device__ float g_nw [2][NL*2*TK]; // NW scores, [line][t] t in 0..19 (10..19 = flipped)
static __device__ int   g_match[2][NL];

// Unfused helpers (match XLA's per-op rounding; no FMA contraction)
__device__ __forceinline__ float fm(float a, float b) { return __fmul_rn(a, b); }
__device__ __forceinline__ float fa(float a, float b) { return __fadd_rn(a, b); }
__device__ __forceinline__ float fs(float a, float b) { return __fsub_rn(a, b); }

// ---------------- kernel 1: sample points + bilinear descriptors -------------
__device__ __forceinline__ float gat(const float* img, int x, int y) {
    if (x < 0 || x >= WW || y < 0 || y >= HH) return 0.0f;
    return img[y*WW + x];
}

__global__ void sample_kernel(const float* __restrict__ seg1,
                              const float* __restrict__ seg2,
                              const float* __restrict__ desc1,
                              const float* __restrict__ desc2) {
    int warp = (blockIdx.x * blockDim.x + threadIdx.x) >> 5;
    int lane = threadIdx.x & 31;
    if (warp >= 2*NPTS) return;
    int set  = warp / NPTS;
    int p    = warp - set*NPTS;
    int line = p / NS;
    int k    = p - line*NS;

    const float* seg  = set ? seg2  : seg1;
    const float* desc = set ? desc2 : desc1;
    float*       dout = set ? g_d2  : g_d1;

    float sy = seg[line*4+0], sx = seg[line*4+1];
    float ey = seg[line*4+2], ex = seg[line*4+3];
    float dy = fs(ey, sy), dx = fs(ex, sx);
    float len = sqrtf(fa(fm(dy, dy), fm(dx, dx)));
    float ns  = fminf(fmaxf(floorf(__fdiv_rn(len, 8.0f)), 2.0f), 5.0f);
    if (k == 0 && lane == 0) g_ns[set][line] = ns;

    float nm1 = fs(ns, 1.0f);
    float ivy = __fdiv_rn(dy, nm1);
    float ivx = __fdiv_rn(dx, nm1);
    float kf  = (float)k;
    float py  = fa(sy, fm(kf, ivy));
    float px  = fa(sx, fm(kf, ivx));
    if (!(kf < ns)) { py = 0.0f; px = 0.0f; }   // reference zeroes invalid pts

    // bilinear coords (img_h = img_w = 512); mirror reference op-for-op
    float xn  = fs(__fdiv_rn(fm(2.0f, px), (float)(WW*4 - 1)), 1.0f);
    float yn  = fs(__fdiv_rn(fm(2.0f, py), (float)(HH*4 - 1)), 1.0f);
    float ixf = __fdiv_rn(fs(fm(fa(xn, 1.0f), (float)WW), 1.0f), 2.0f);
    float iyf = __fdiv_rn(fs(fm(fa(yn, 1.0f), (float)HH), 1.0f), 2.0f);
    float x0f = floorf(ixf), y0f = floorf(iyf);
    float wx = fs(ixf, x0f), wy = fs(iyf, y0f);
    int   x0 = (int)x0f,  y0 = (int)y0f;
    float w00 = fm(fs(1.0f, wx), fs(1.0f, wy));
    float w10 = fm(wx, fs(1.0f, wy));
    float w01 = fm(fs(1.0f, wx), wy);
    float w11 = fm(wx, wy);

    // Each lane holds dims {lane, lane+32, lane+64, lane+96}; partial sum of
    // squares strided-ascending with separate mul/add, then 32-lane tree.
    float v[4];
    float ss = 0.0f;
    #pragma unroll
    for (int q = 0; q < 4; q++) {
        int d = lane + q*32;
        const float* img = desc + d*HH*WW;
        float a = fm(gat(img, x0,   y0  ), w00);
        a = fa(a, fm(gat(img, x0+1, y0  ), w10));
        a = fa(a, fm(gat(img, x0,   y0+1), w01));
        a = fa(a, fm(gat(img, x0+1, y0+1), w11));
        v[q] = a;
        ss = fa(ss, fm(a, a));
    }
    #pragma unroll
    for (int off = 16; off; off >>= 1)
        ss = fa(ss, __shfl_xor_sync(0xffffffffu, ss, off));
    float nrm = sqrtf(ss);
    #pragma unroll
    for (int q = 0; q < 4; q++)
        dout[p*DD + lane + q*32] = __fdiv_rn(v[q], nrm);   // IEEE division like XLA
}

// ------------- kernel 2: fused GEMM + 5x5-block line-score reduction ---------
// 16x16 line-pairs per block (80x80 samples), K chunks of 32; accumulation is
// sequential k=0..127 single-accumulator FFMA == cuBLAS sgemm rounding.
__global__ void ls_kernel() {
    __shared__ float s1[80][33];
    __shared__ float s2[80][33];
    const int i0 = blockIdx.y * 16;
    const int j0 = blockIdx.x * 16;
    const int t  = threadIdx.x;           // 256 threads
    const int li = t >> 4;
    const int lj = t & 15;

    float acc[5][5];
    #pragma unroll
    for (int n = 0; n < 5; n++)
        #pragma unroll
        for (int m = 0; m < 5; m++) acc[n][m] = 0.0f;

    for (int k0 = 0; k0 < DD; k0 += 32) {
        #pragma unroll
        for (int it = 0; it < 10; it++) {          // 2560 elems / 256 threads
            int idx = t + it*256;
            int r   = idx >> 5;
            int kk  = idx & 31;
            s1[r][kk] = g_d1[(i0*NS + r)*DD + k0 + kk];
            s2[r][kk] = g_d2[(j0*NS + r)*DD + k0 + kk];
        }
        __syncthreads();
        #pragma unroll
        for (int kk = 0; kk < 32; kk++) {
            float a[5], b[5];
            #pragma unroll
            for (int n = 0; n < 5; n++) a[n] = s1[li*5 + n][kk];
            #pragma unroll
            for (int m = 0; m < 5; m++) b[m] = s2[lj*5 + m][kk];
            #pragma unroll
            for (int n = 0; n < 5; n++)
                #pragma unroll
                for (int m = 0; m < 5; m++)
                    acc[n][m] = __fmaf_rn(a[n], b[m], acc[n][m]);
        }
        __syncthreads();
    }

    int nsa = (int)g_ns[0][i0 + li];
    int nsb = (int)g_ns[1][j0 + lj];

    // masked block: s[n][m] = (n<nsa && m<nsb) ? dot : -1
    float ls1s = 0.0f, c1 = 0.0f;
    #pragma unroll
    for (int n = 0; n < 5; n++) {
        float mx = -3.0e38f;
        #pragma unroll
        for (int m = 0; m < 5; m++) {
            float sv = (n < nsa && m < nsb) ? acc[n][m] : -1.0f;
            mx = fmaxf(mx, sv);
        }
        float v1 = (mx != -1.0f) ? 1.0f : 0.0f;
        ls1s = fa(ls1s, fm(mx, v1)); c1 = fa(c1, v1);
    }
    float ls2s = 0.0f, c2 = 0.0f;
    #pragma unroll
    for (int m = 0; m < 5; m++) {
        float mx = -3.0e38f;
        #pragma unroll
        for (int n = 0; n < 5; n++) {
            float sv = (n < nsa && m < nsb) ? acc[n][m] : -1.0f;
            mx = fmaxf(mx, sv);
        }
        float v2 = (mx != -1.0f) ? 1.0f : 0.0f;
        ls2s = fa(ls2s, fm(mx, v2)); c2 = fa(c2, v2);
    }
    float lsc = __fdiv_rn(fa(__fdiv_rn(ls1s, c1), __fdiv_rn(ls2s, c2)), 2.0f);
    g_ls [(i0+li)*NL + (j0+lj)] = lsc;
    g_lsT[(j0+lj)*NL + (i0+li)] = lsc;
}

// ---------------- kernel 3: top-10 selection (argsort-compatible) ------------
// Key = (monotonic float bits, index): descending selection breaks value ties
// toward larger index == last-10 of a stable ascending argsort.
__global__ void topk_kernel() {
    int row = blockIdx.x;
    int dir = blockIdx.y;
    int t   = threadIdx.x;                 // 128 threads
    const float* ls = dir ? g_lsT : g_ls;
    __shared__ unsigned long long sb[128];

    unsigned long long prev = 0xFFFFFFFFFFFFFFFFull;
    for (int s = 0; s < TK; s++) {
        unsigned long long best = 0ull;
        for (int j = t; j < NL; j += 128) {
            float v = ls[row*NL + j];
            unsigned u = __float_as_uint(v);
            u = (u & 0x80000000u) ? ~u : (u | 0x80000000u);
            unsigned long long key = ((unsigned long long)u << 32) | (unsigned)j;
            if (key < prev && key > best) best = key;
        }
        sb[t] = best;
        __syncthreads();
        #pragma unroll
        for (int off = 64; off; off >>= 1) {
            if (t < off) { if (sb[t+off] > sb[t]) sb[t] = sb[t+off]; }
            __syncthreads();
        }
        prev = sb[0];
        if (t == 0) g_topk[dir][row*TK + (TK-1-s)] = (int)(prev & 0xFFFFFFFFull);
        __syncthreads();
    }
}

// ---------------- kernel 4: recompute 5x5 blocks + Needleman-Wunsch ----------
// One warp per (dir,line,candidate). Lane l<25 computes dot (n=l/5, m=l%5)
// sequentially over k=0..127 with single-accumulator FFMA == cuBLAS rounding.
// float4 loads: identical accumulation order (x,y,z,w sequential), 4x fewer
// LDG instructions -> 4x fewer L1tex wavefronts (the r4 bottleneck).
__global__ void nw_kernel() {
    int gw   = (blockIdx.x * blockDim.x + threadIdx.x) >> 5;
    int lane = threadIdx.x & 31;
    if (gw >= 2*NL*2*TK) return;
    int dir  = gw / (NL*2*TK);
    int rem  = gw - dir*(NL*2*TK);
    int line = rem / (2*TK);
    int t    = rem - line*(2*TK);
    int j    = g_topk[dir][line*TK + (t % TK)];
    int flip = (t >= TK);

    const float* dA = dir ? g_d2 : g_d1;   // row samples
    const float* dB = dir ? g_d1 : g_d2;   // col samples
    int na = (int)g_ns[dir ? 1 : 0][line];
    int nb = (int)g_ns[dir ? 0 : 1][j];

    const float* pa = dA + (line*NS)*DD;
    const float* pb = dB + (j*NS)*DD;

    int n = lane / 5, m = lane - n*5;
    float acc = 0.0f;
    if (lane < 25) {
        const float4* ra = (const float4*)(pa + n*DD);
        const float4* rb = (const float4*)(pb + m*DD);
        #pragma unroll 8
        for (int k4 = 0; k4 < DD/4; k4++) {
            float4 a = ra[k4];
            float4 b = rb[k4];
            acc = __fmaf_rn(a.x, b.x, acc);
            acc = __fmaf_rn(a.y, b.y, acc);
            acc = __fmaf_rn(a.z, b.z, acc);
            acc = __fmaf_rn(a.w, b.w, acc);
        }
    }

    // Broadcast the 25 dots to ALL lanes (every lane must execute each shfl).
    float blk[25];
    #pragma unroll
    for (int i = 0; i < 25; i++)
        blk[i] = __shfl_sync(0xffffffffu, acc, i);

    if (lane == 0) {
        float prev[6] = {0,0,0,0,0,0};
        #pragma unroll
        for (int r = 0; r < 5; r++) {
            float cur[6]; cur[0] = 0.0f;
            #pragma unroll
            for (int c = 0; c < 5; c++) {
                int sm = flip ? (4 - c) : c;
                float sv = (r < na && sm < nb) ? blk[r*5 + sm] : -1.0f;
                sv = fs(sv, GAPF);
                cur[c+1] = fmaxf(fmaxf(cur[c], prev[c+1]), fa(prev[c], sv));
            }
            #pragma unroll
            for (int c = 0; c < 6; c++) prev[c] = cur[c];
        }
        g_nw[dir][line*2*TK + t] = prev[5];
    }
}

// ---------------- kernel 5: argmax over 20 candidates ------------------------
__global__ void argmax_kernel() {
    int idx = blockIdx.x * blockDim.x + threadIdx.x;
    if (idx >= 2*NL) return;
    int dir = idx / NL, line = idx - dir*NL;
    const float* nw = &g_nw[dir][line*2*TK];
    float best = nw[0]; int bi = 0;
    for (int t = 1; t < 2*TK; t++)
        if (nw[t] > best) { best = nw[t]; bi = t; }   // first-occurrence argmax
    g_match[dir][line] = g_topk[dir][line*TK + (bi % TK)];
}

// ---------------- kernel 6: mutual check + write output ----------------------
// out layout (float32): [0,1200) matches, [1200, 25200) nw (dir-1), row-major.
__global__ void final_kernel(float* __restrict__ out, int out_size) {
    int idx = blockIdx.x * blockDim.x + threadIdx.x;
    if (idx >= NL + NL*2*TK || idx >= out_size) return;
    if (idx < NL) {
        int m  = g_match[0][idx];
        int ok = (g_match[1][m] == idx);
        out[idx] = ok ? (float)m : -1.0f;
    } else {
        out[idx] = g_nw[0][idx - NL];
    }
}

// ---------------- launcher ---------------------------------------------------
extern "C" void kernel_launch(void* const* d_in, const int* in_sizes, int n_in,
                              void* d_out, int out_size) {
    const float* seg1  = (const float*)d_in[0];
    const float* seg2  = (const float*)d_in[1];
    const float* desc1 = (const float*)d_in[2];
    const float* desc2 = (const float*)d_in[3];

    {   // 2*6000 points, one warp each
        int warps = 2*NPTS;
        int threads = warps*32;
        sample_kernel<<<(threads + 255)/256, 256>>>(seg1, seg2, desc1, desc2);
    }
    {
        dim3 g(NL/16, NL/16);
        ls_kernel<<<g, 256>>>();
    }
    topk_kernel<<<dim3(NL, 2), 128>>>();
    {
        int warps = 2*NL*2*TK;
        nw_kernel<<<(warps*32 + 255)/256, 256>>>();
    }
    argmax_kernel<<<(2*NL + 255)/256, 256>>>();
    final_kernel<<<(NL + NL*2*TK + 255)/256, 256>>>((float*)d_out, out_size);
}

// round 6
// speedup vs baseline: 1.3569x; 1.1495x over previous
#include <cuda_runtime.h>
#include <math.h>

#define NL   1200
#define NS   5
#define NPTS (NL*NS)     // 6000
#define DD   128
#define HH   128
#define WW   128
#define TK   10
#define GAPF 0.1f

// ---------------- scratch (static __device__, no allocations) ----------------
static __device__ float g_d1[NPTS*DD];     // normalized descriptors set1 [point][dim]
static __device__ float g_d2[NPTS*DD];     // set2
static __device__ float g_ns[2][NL];       // nsamp per line (float, integer-valued 2..5)
static __device__ float g_ls [NL*NL];      // line_scores[i][j]
static __device__ float g_lsT[NL*NL];      // transpose, for direction-2 topk
static __device__ int   g_topk[2][NL*TK];  // top-10 indices, pos 9 = largest (argsort order)
static __device__ float g_nw [2][NL*2*TK]; // NW scores, [line][t] t in 0..19 (10..19 = flipped)
static __device__ int   g_match[2][NL];

// Unfused helpers (match XLA's per-op rounding; no FMA contraction)
__device__ __forceinline__ float fm(float a, float b) { return __fmul_rn(a, b); }
__device__ __forceinline__ float fa(float a, float b) { return __fadd_rn(a, b); }
__device__ __forceinline__ float fs(float a, float b) { return __fsub_rn(a, b); }

// Packed f32x2 FMA (Blackwell). Each 32-bit lane rounds identically to FFMA.
__device__ __forceinline__ void fma2(unsigned long long& d,
                                     unsigned long long a,
                                     unsigned long long b) {
    asm("fma.rn.f32x2 %0, %1, %2, %0;" : "+l"(d) : "l"(a), "l"(b));
}
__device__ __forceinline__ void upk2(unsigned long long v, float& lo, float& hi) {
    asm("mov.b64 {%0, %1}, %2;" : "=f"(lo), "=f"(hi) : "l"(v));
}

// ---------------- kernel 1: sample points + bilinear descriptors -------------
__device__ __forceinline__ float gat(const float* img, int x, int y) {
    if (x < 0 || x >= WW || y < 0 || y >= HH) return 0.0f;
    return img[y*WW + x];
}

__global__ void sample_kernel(const float* __restrict__ seg1,
                              const float* __restrict__ seg2,
                              const float* __restrict__ desc1,
                              const float* __restrict__ desc2) {
    int warp = (blockIdx.x * blockDim.x + threadIdx.x) >> 5;
    int lane = threadIdx.x & 31;
    if (warp >= 2*NPTS) return;
    int set  = warp / NPTS;
    int p    = warp - set*NPTS;
    int line = p / NS;
    int k    = p - line*NS;

    const float* seg  = set ? seg2  : seg1;
    const float* desc = set ? desc2 : desc1;
    float*       dout = set ? g_d2  : g_d1;

    float sy = seg[line*4+0], sx = seg[line*4+1];
    float ey = seg[line*4+2], ex = seg[line*4+3];
    float dy = fs(ey, sy), dx = fs(ex, sx);
    float len = sqrtf(fa(fm(dy, dy), fm(dx, dx)));
    float ns  = fminf(fmaxf(floorf(__fdiv_rn(len, 8.0f)), 2.0f), 5.0f);
    if (k == 0 && lane == 0) g_ns[set][line] = ns;

    float nm1 = fs(ns, 1.0f);
    float ivy = __fdiv_rn(dy, nm1);
    float ivx = __fdiv_rn(dx, nm1);
    float kf  = (float)k;
    float py  = fa(sy, fm(kf, ivy));
    float px  = fa(sx, fm(kf, ivx));
    if (!(kf < ns)) { py = 0.0f; px = 0.0f; }   // reference zeroes invalid pts

    // bilinear coords (img_h = img_w = 512); mirror reference op-for-op
    float xn  = fs(__fdiv_rn(fm(2.0f, px), (float)(WW*4 - 1)), 1.0f);
    float yn  = fs(__fdiv_rn(fm(2.0f, py), (float)(HH*4 - 1)), 1.0f);
    float ixf = __fdiv_rn(fs(fm(fa(xn, 1.0f), (float)WW), 1.0f), 2.0f);
    float iyf = __fdiv_rn(fs(fm(fa(yn, 1.0f), (float)HH), 1.0f), 2.0f);
    float x0f = floorf(ixf), y0f = floorf(iyf);
    float wx = fs(ixf, x0f), wy = fs(iyf, y0f);
    int   x0 = (int)x0f,  y0 = (int)y0f;
    float w00 = fm(fs(1.0f, wx), fs(1.0f, wy));
    float w10 = fm(wx, fs(1.0f, wy));
    float w01 = fm(fs(1.0f, wx), wy);
    float w11 = fm(wx, wy);

    float v[4];
    float ss = 0.0f;
    #pragma unroll
    for (int q = 0; q < 4; q++) {
        int d = lane + q*32;
        const float* img = desc + d*HH*WW;
        float a = fm(gat(img, x0,   y0  ), w00);
        a = fa(a, fm(gat(img, x0+1, y0  ), w10));
        a = fa(a, fm(gat(img, x0,   y0+1), w01));
        a = fa(a, fm(gat(img, x0+1, y0+1), w11));
        v[q] = a;
        ss = fa(ss, fm(a, a));
    }
    #pragma unroll
    for (int off = 16; off; off >>= 1)
        ss = fa(ss, __shfl_xor_sync(0xffffffffu, ss, off));
    float nrm = sqrtf(ss);
    #pragma unroll
    for (int q = 0; q < 4; q++)
        dout[p*DD + lane + q*32] = __fdiv_rn(v[q], nrm);   // IEEE division like XLA
}

// ------------- kernel 2: fused GEMM + 5x5-block line-score reduction ---------
// 16x16 line-pairs per block. Packed f32x2 FMA: each accumulator still sums
// k=0..127 sequentially with per-lane IEEE fp32 rounding == previous kernel
// bit-for-bit. s1 stored as duplicated pairs (a,a); s2 stored kk-major so
// (b[m],b[m+1]) load as one 8B LDS.
__global__ void ls_kernel() {
    __shared__ __align__(16) float s1d[32][194];   // [kk][row*2 {dup}] rows 0..79
    __shared__ __align__(16) float s2t[32][102];   // [kk][lj*6 + m], col lj*6+5 = 0 pad
    const int i0 = blockIdx.y * 16;
    const int j0 = blockIdx.x * 16;
    const int t  = threadIdx.x;           // 256 threads
    const int li = t >> 4;
    const int lj = t & 15;

    unsigned long long accp[5][3];        // m-pairs (0,1) (2,3) (4,pad0)
    #pragma unroll
    for (int n = 0; n < 5; n++)
        #pragma unroll
        for (int p = 0; p < 3; p++) accp[n][p] = 0ull;

    // zero the pad columns (read as hi half of the m=4 pair; never re-written)
    for (int i = t; i < 512; i += 256) {
        int kk = i & 31, g = i >> 5;
        s2t[kk][g*6 + 5] = 0.0f;
    }

    for (int k0 = 0; k0 < DD; k0 += 32) {
        #pragma unroll
        for (int it = 0; it < 10; it++) {          // 2560 elems / 256 threads
            int idx = t + it*256;
            int r   = idx >> 5;
            int kk  = idx & 31;
            float v1 = g_d1[(i0*NS + r)*DD + k0 + kk];
            *(float2*)&s1d[kk][r*2] = make_float2(v1, v1);
            int rl = r / 5, rm = r - rl*5;
            s2t[kk][rl*6 + rm] = g_d2[(j0*NS + r)*DD + k0 + kk];
        }
        __syncthreads();
        #pragma unroll
        for (int kk = 0; kk < 32; kk++) {
            unsigned long long b01 = *(const unsigned long long*)&s2t[kk][lj*6];
            unsigned long long b23 = *(const unsigned long long*)&s2t[kk][lj*6 + 2];
            unsigned long long b4p = *(const unsigned long long*)&s2t[kk][lj*6 + 4];
            #pragma unroll
            for (int n = 0; n < 5; n++) {
                unsigned long long a2 = *(const unsigned long long*)&s1d[kk][(li*5 + n)*2];
                fma2(accp[n][0], a2, b01);
                fma2(accp[n][1], a2, b23);
                fma2(accp[n][2], a2, b4p);
            }
        }
        __syncthreads();
    }

    float acc[5][5];
    #pragma unroll
    for (int n = 0; n < 5; n++) {
        float dead;
        upk2(accp[n][0], acc[n][0], acc[n][1]);
        upk2(accp[n][1], acc[n][2], acc[n][3]);
        upk2(accp[n][2], acc[n][4], dead);
    }

    int nsa = (int)g_ns[0][i0 + li];
    int nsb = (int)g_ns[1][j0 + lj];

    // masked block: s[n][m] = (n<nsa && m<nsb) ? dot : -1
    float ls1s = 0.0f, c1 = 0.0f;
    #pragma unroll
    for (int n = 0; n < 5; n++) {
        float mx = -3.0e38f;
        #pragma unroll
        for (int m = 0; m < 5; m++) {
            float sv = (n < nsa && m < nsb) ? acc[n][m] : -1.0f;
            mx = fmaxf(mx, sv);
        }
        float v1 = (mx != -1.0f) ? 1.0f : 0.0f;
        ls1s = fa(ls1s, fm(mx, v1)); c1 = fa(c1, v1);
    }
    float ls2s = 0.0f, c2 = 0.0f;
    #pragma unroll
    for (int m = 0; m < 5; m++) {
        float mx = -3.0e38f;
        #pragma unroll
        for (int n = 0; n < 5; n++) {
            float sv = (n < nsa && m < nsb) ? acc[n][m] : -1.0f;
            mx = fmaxf(mx, sv);
        }
        float v2 = (mx != -1.0f) ? 1.0f : 0.0f;
        ls2s = fa(ls2s, fm(mx, v2)); c2 = fa(c2, v2);
    }
    float lsc = __fdiv_rn(fa(__fdiv_rn(ls1s, c1), __fdiv_rn(ls2s, c2)), 2.0f);
    g_ls [(i0+li)*NL + (j0+lj)] = lsc;
    g_lsT[(j0+lj)*NL + (i0+li)] = lsc;
}

// ---------------- kernel 3: top-10 selection (argsort-compatible) ------------
// Key = (monotonic float bits, index): descending selection breaks value ties
// toward larger index == last-10 of a stable ascending argsort.
__global__ void topk_kernel() {
    int row = blockIdx.x;
    int dir = blockIdx.y;
    int t   = threadIdx.x;                 // 128 threads
    const float* ls = dir ? g_lsT : g_ls;
    __shared__ unsigned long long sb[128];

    unsigned long long prev = 0xFFFFFFFFFFFFFFFFull;
    for (int s = 0; s < TK; s++) {
        unsigned long long best = 0ull;
        for (int j = t; j < NL; j += 128) {
            float v = ls[row*NL + j];
            unsigned u = __float_as_uint(v);
            u = (u & 0x80000000u) ? ~u : (u | 0x80000000u);
            unsigned long long key = ((unsigned long long)u << 32) | (unsigned)j;
            if (key < prev && key > best) best = key;
        }
        sb[t] = best;
        __syncthreads();
        #pragma unroll
        for (int off = 64; off; off >>= 1) {
            if (t < off) { if (sb[t+off] > sb[t]) sb[t] = sb[t+off]; }
            __syncthreads();
        }
        prev = sb[0];
        if (t == 0) g_topk[dir][row*TK + (TK-1-s)] = (int)(prev & 0xFFFFFFFFull);
        __syncthreads();
    }
}

// ---------------- kernel 4: smem-staged 5x5 blocks + Needleman-Wunsch --------
// One block (160 thr = 5 warps) per (dir,line). A tile + 10 candidate B tiles
// staged in smem with coalesced float4 loads. Warp w computes candidates
// 2w, 2w+1; dots keep the exact float4 x,y,z,w sequential accumulation order
// (bit-identical to previous version); lanes 0/1 run fwd/flip DP (dots shared).
__global__ void nw_kernel() {
    __shared__ __align__(16) float sA[5][132];
    __shared__ __align__(16) float sB[10][5][132];
    __shared__ int s_top[10];
    int line = blockIdx.x;
    int dir  = blockIdx.y;
    int t    = threadIdx.x;                 // 160 threads

    const float* dA = dir ? g_d2 : g_d1;
    const float* dB = dir ? g_d1 : g_d2;

    if (t < 10) s_top[t] = g_topk[dir][line*TK + t];
    __syncthreads();

    {   // load A tile: 5 rows x 128 = 160 float4
        int r = t >> 5, c4 = t & 31;
        float4 v = *(const float4*)&dA[(line*NS + r)*DD + c4*4];
        *(float4*)&sA[r][c4*4] = v;
    }
    #pragma unroll
    for (int i = 0; i < 10; i++) {          // 10 B tiles
        int j = s_top[i];
        int r = t >> 5, c4 = t & 31;
        float4 v = *(const float4*)&dB[(j*NS + r)*DD + c4*4];
        *(float4*)&sB[i][r][c4*4] = v;
    }
    __syncthreads();

    int warp = t >> 5, lane = t & 31;
    int na = (int)g_ns[dir][line];
    int n = lane / 5, m = lane - n*5;

    #pragma unroll
    for (int cc = 0; cc < 2; cc++) {
        int c = warp*2 + cc;                // candidate 0..9
        int j = s_top[c];
        int nb = (int)g_ns[1-dir][j];

        float acc = 0.0f;
        if (lane < 25) {
            const float4* ra = (const float4*)&sA[n][0];
            const float4* rb = (const float4*)&sB[c][m][0];
            #pragma unroll 8
            for (int k4 = 0; k4 < DD/4; k4++) {
                float4 a = ra[k4];
                float4 b = rb[k4];
                acc = __fmaf_rn(a.x, b.x, acc);
                acc = __fmaf_rn(a.y, b.y, acc);
                acc = __fmaf_rn(a.z, b.z, acc);
                acc = __fmaf_rn(a.w, b.w, acc);
            }
        }
        // broadcast 25 dots to all lanes
        float blk[25];
        #pragma unroll
        for (int i = 0; i < 25; i++)
            blk[i] = __shfl_sync(0xffffffffu, acc, i);

        if (lane < 2) {
            int flip = lane;
            float prev[6] = {0,0,0,0,0,0};
            #pragma unroll
            for (int r = 0; r < 5; r++) {
                float cur[6]; cur[0] = 0.0f;
                #pragma unroll
                for (int cI = 0; cI < 5; cI++) {
                    int sm = flip ? (4 - cI) : cI;
                    float sv = (r < na && sm < nb) ? blk[r*5 + sm] : -1.0f;
                    sv = fs(sv, GAPF);
                    cur[cI+1] = fmaxf(fmaxf(cur[cI], prev[cI+1]), fa(prev[cI], sv));
                }
                #pragma unroll
                for (int cI = 0; cI < 6; cI++) prev[cI] = cur[cI];
            }
            g_nw[dir][line*2*TK + flip*TK + c] = prev[5];
        }
    }
}

// ---------------- kernel 5: argmax over 20 candidates ------------------------
__global__ void argmax_kernel() {
    int idx = blockIdx.x * blockDim.x + threadIdx.x;
    if (idx >= 2*NL) return;
    int dir = idx / NL, line = idx - dir*NL;
    const float* nw = &g_nw[dir][line*2*TK];
    float best = nw[0]; int bi = 0;
    for (int t = 1; t < 2*TK; t++)
        if (nw[t] > best) { best = nw[t]; bi = t; }   // first-occurrence argmax
    g_match[dir][line] = g_topk[dir][line*TK + (bi % TK)];
}

// ---------------- kernel 6: mutual check + write output ----------------------
// out layout (float32): [0,1200) matches, [1200, 25200) nw (dir-1), row-major.
__global__ void final_kernel(float* __restrict__ out, int out_size) {
    int idx = blockIdx.x * blockDim.x + threadIdx.x;
    if (idx >= NL + NL*2*TK || idx >= out_size) return;
    if (idx < NL) {
        int m  = g_match[0][idx];
        int ok = (g_match[1][m] == idx);
        out[idx] = ok ? (float)m : -1.0f;
    } else {
        out[idx] = g_nw[0][idx - NL];
    }
}

// ---------------- launcher ---------------------------------------------------
extern "C" void kernel_launch(void* const* d_in, const int* in_sizes, int n_in,
                              void* d_out, int out_size) {
    const float* seg1  = (const float*)d_in[0];
    const float* seg2  = (const float*)d_in[1];
    const float* desc1 = (const float*)d_in[2];
    const float* desc2 = (const float*)d_in[3];

    {   // 2*6000 points, one warp each
        int warps = 2*NPTS;
        int threads = warps*32;
        sample_kernel<<<(threads + 255)/256, 256>>>(seg1, seg2, desc1, desc2);
    }
    {
        dim3 g(NL/16, NL/16);
        ls_kernel<<<g, 256>>>();
    }
    topk_kernel<<<dim3(NL, 2), 128>>>();
    nw_kernel<<<dim3(NL, 2), 160>>>();
    argmax_kernel<<<(2*NL + 255)/256, 256>>>();
    final_kernel<<<(NL + NL*2*TK + 255)/256, 256>>>((float*)d_out, out_size);
}